// round 15
// baseline (speedup 1.0000x reference)
#include <cuda_runtime.h>
#include <cuda_fp16.h>
#include <cstdint>

// Problem constants (from reference setup_inputs)
#define NMAX 8192
#define D    128
#define MASK_WORDS ((size_t)NMAX * NMAX / 32)   // 2,097,152 words = 8 MB
#define CAP  2048                               // neighbor-list capacity per row

// Scratch (static device globals — no allocation in kernel_launch)
// g_mask is zero-initialized at module load; k_aggregate re-zeroes the rows it
// consumes, so the mask is all-zero again at the end of every kernel_launch.
__device__ unsigned g_mask[MASK_WORDS];          // adjacency bitmask, row = src
__device__ int      g_deg[NMAX];                 // distinct-neighbor degree (incl. self loop)
__device__ __half2  g_yh[NMAX * 64];             // y' = dinv[row]*(x@W^T)[row], fp16
__device__ float2   g_wt2[64 * D];               // W^T packed k-pair-interleaved

// packed dual-fp32 fma: d.lo += a.lo*b.lo ; d.hi += a.hi*b.hi
__device__ __forceinline__ void ffma2(unsigned long long& d,
                                      unsigned long long a,
                                      unsigned long long b) {
    asm("fma.rn.f32x2 %0, %1, %2, %0;" : "+l"(d) : "l"(a), "l"(b));
}
__device__ __forceinline__ float f32x2_hsum(unsigned long long v) {
    float lo, hi;
    asm("mov.b64 {%0,%1}, %2;" : "=f"(lo), "=f"(hi) : "l"(v));
    return lo + hi;
}
// packed fp16 add on raw uint32 half2 bits
__device__ __forceinline__ unsigned hadd2(unsigned a, unsigned b) {
    unsigned r;
    asm("add.rn.f16x2 %0, %1, %2;" : "=r"(r) : "r"(a), "r"(b));
    return r;
}
__device__ __forceinline__ float2 h2f2(unsigned s) {
    return __half22float2(*reinterpret_cast<__half2*>(&s));
}

// ---------------------------------------------------------------------------
// 1) zero degree + pack Wt2 (mask zeroing lives in k_aggregate's epilogue)
__global__ void k_zero(const float* __restrict__ W, int n) {
    int i = blockIdx.x * blockDim.x + threadIdx.x;
    if (i < n) g_deg[i] = 0;
    if (i < 64 * D) {
        int col = i & 127;
        int kp  = i >> 7;
        g_wt2[kp * D + col] = make_float2(W[col * D + 2 * kp],
                                          W[col * D + 2 * kp + 1]);
    }
}

// ---------------------------------------------------------------------------
// 2) set bits for edges (+ self loops), count degrees on first-set only (dedup)
//    edge_index is int32 (JAX x64-disabled downcasts the requested int64)
__global__ void k_build(const int* __restrict__ edge, int E, int N) {
    int t = blockIdx.x * blockDim.x + threadIdx.x;
    int total = E + N;
    if (t >= total) return;
    int s, d;
    if (t < E) {
        s = edge[t];        // edge_index[0, t] = src
        d = edge[E + t];    // edge_index[1, t] = dst
    } else {
        s = d = t - E;      // self loop
    }
    s &= (NMAX - 1);
    d &= (NMAX - 1);
    int bitpos = s * N + d;
    unsigned bit = 1u << (bitpos & 31);
    unsigned old = atomicOr(&g_mask[bitpos >> 5], bit);
    if (!(old & bit)) atomicAdd(&g_deg[s], 1);
}

// ---------------------------------------------------------------------------
// 3) y' = dinv .* (x @ W^T)  via packed f32x2 FMA, fp16 output.
//    32 rows/block, 256 threads: cp = t&63 -> cols (2cp, 2cp+1),
//    ry = t>>6 -> rows 8ry..8ry+7 (8 rows/thread halves W L2 traffic vs BR=16).
//    W register-prefetched DEPTH 2.
#define BR 32
__global__ void __launch_bounds__(256) k_gemm_y(const float* __restrict__ x, int N) {
    __shared__ float4 xs[BR * 32];   // [row][kk4], 16 KB

    int t = threadIdx.x;             // 0..255
    int row0 = blockIdx.x * BR;

    // load 32x128 x-tile (1024 float4, 4 per thread), guard tail
    const float4* xg = reinterpret_cast<const float4*>(x) + (size_t)row0 * 32;
    int lim = (N - row0) * 32;
    #pragma unroll
    for (int q = 0; q < 4; q++) {
        int idx = t + q * 256;
        xs[idx] = (idx < lim) ? xg[idx] : make_float4(0.f, 0.f, 0.f, 0.f);
    }
    __syncthreads();

    int cp = t & 63;                 // col-pair: cols 2cp, 2cp+1
    int ry = t >> 6;                 // 0..3 -> rows 8ry..8ry+7
    int r0 = 8 * ry;

    const ulonglong2* xv = reinterpret_cast<const ulonglong2*>(xs);
    const ulonglong2* wv = reinterpret_cast<const ulonglong2*>(g_wt2);

    unsigned long long acc[8][2];
    #pragma unroll
    for (int r = 0; r < 8; r++) { acc[r][0] = 0ull; acc[r][1] = 0ull; }

    // depth-2 W prefetch: wa = current kk, wb = next kk
    ulonglong2 wa0 = wv[0 * 64 + cp], wa1 = wv[1 * 64 + cp];   // kk = 0
    ulonglong2 wb0 = wv[2 * 64 + cp], wb1 = wv[3 * 64 + cp];   // kk = 1

    #pragma unroll 8
    for (int kk = 0; kk < 32; kk++) {
        ulonglong2 nw0, nw1;
        if (kk < 30) {                          // prefetch kk+2's W pair
            nw0 = wv[(2 * kk + 4) * 64 + cp];
            nw1 = wv[(2 * kk + 5) * 64 + cp];
        }
        // first 4 rows
        {
            ulonglong2 xa0 = xv[(r0 + 0) * 32 + kk];
            ulonglong2 xa1 = xv[(r0 + 1) * 32 + kk];
            ulonglong2 xa2 = xv[(r0 + 2) * 32 + kk];
            ulonglong2 xa3 = xv[(r0 + 3) * 32 + kk];
            ffma2(acc[0][0], xa0.x, wa0.x); ffma2(acc[0][1], xa0.x, wa0.y);
            ffma2(acc[1][0], xa1.x, wa0.x); ffma2(acc[1][1], xa1.x, wa0.y);
            ffma2(acc[2][0], xa2.x, wa0.x); ffma2(acc[2][1], xa2.x, wa0.y);
            ffma2(acc[3][0], xa3.x, wa0.x); ffma2(acc[3][1], xa3.x, wa0.y);
            ffma2(acc[0][0], xa0.y, wa1.x); ffma2(acc[0][1], xa0.y, wa1.y);
            ffma2(acc[1][0], xa1.y, wa1.x); ffma2(acc[1][1], xa1.y, wa1.y);
            ffma2(acc[2][0], xa2.y, wa1.x); ffma2(acc[2][1], xa2.y, wa1.y);
            ffma2(acc[3][0], xa3.y, wa1.x); ffma2(acc[3][1], xa3.y, wa1.y);
        }
        // second 4 rows
        {
            ulonglong2 xa4 = xv[(r0 + 4) * 32 + kk];
            ulonglong2 xa5 = xv[(r0 + 5) * 32 + kk];
            ulonglong2 xa6 = xv[(r0 + 6) * 32 + kk];
            ulonglong2 xa7 = xv[(r0 + 7) * 32 + kk];
            ffma2(acc[4][0], xa4.x, wa0.x); ffma2(acc[4][1], xa4.x, wa0.y);
            ffma2(acc[5][0], xa5.x, wa0.x); ffma2(acc[5][1], xa5.x, wa0.y);
            ffma2(acc[6][0], xa6.x, wa0.x); ffma2(acc[6][1], xa6.x, wa0.y);
            ffma2(acc[7][0], xa7.x, wa0.x); ffma2(acc[7][1], xa7.x, wa0.y);
            ffma2(acc[4][0], xa4.y, wa1.x); ffma2(acc[4][1], xa4.y, wa1.y);
            ffma2(acc[5][0], xa5.y, wa1.x); ffma2(acc[5][1], xa5.y, wa1.y);
            ffma2(acc[6][0], xa6.y, wa1.x); ffma2(acc[6][1], xa6.y, wa1.y);
            ffma2(acc[7][0], xa7.y, wa1.x); ffma2(acc[7][1], xa7.y, wa1.y);
        }
        wa0 = wb0; wa1 = wb1;
        wb0 = nw0; wb1 = nw1;
    }

    #pragma unroll
    for (int r = 0; r < 8; r++) {
        int row = row0 + r0 + r;
        if (row < N) {
            float dv = rsqrtf((float)g_deg[row] + 1e-8f);
            float sx = f32x2_hsum(acc[r][0]) * dv;
            float sy = f32x2_hsum(acc[r][1]) * dv;
            g_yh[(size_t)row * 64 + cp] = __floats2half2_rn(sx, sy);
        }
    }
}

// ---------------------------------------------------------------------------
// 4) out[i] = dinv[i] * sum_{j in nbr(i)} y'[j]  + b
//    Phase A: direct uint2 mask load + warp scans + ordered emit.
//    Phase B: 4 streams x 32 threads, uint2 (4 cols) per neighbor,
//    HADD2 tree per 4 neighbors, fp32 master accumulators, fixed-order
//    4-way reduce. Deterministic.
//    Epilogue: re-zero this row's mask words.
__global__ void k_aggregate(const float* __restrict__ bias,
                            float* __restrict__ out, int N) {
    int i = blockIdx.x;
    int t = threadIdx.x;   // 0..127
    int words = N >> 5;    // 256

    __shared__ unsigned short nbr[CAP];      // 4 KB
    __shared__ float2 part[4 * 64];          // 2 KB
    __shared__ int wsum[4];
    __shared__ int totK;

    // direct global load: thread t owns words 2t, 2t+1 (coalesced uint2)
    uint2* mrow = reinterpret_cast<uint2*>(g_mask + (size_t)i * words);
    uint2 mw = mrow[t];
    unsigned m0 = mw.x, m1 = mw.y;
    int cnt = __popc(m0) + __popc(m1);

    // inclusive warp scan of counts
    int lane = t & 31, wid = t >> 5;
    int inc = cnt;
    #pragma unroll
    for (int dd = 1; dd < 32; dd <<= 1) {
        int v = __shfl_up_sync(0xffffffffu, inc, dd);
        if (lane >= dd) inc += v;
    }
    if (lane == 31) wsum[wid] = inc;
    __syncthreads();
    int wbase = 0;
    #pragma unroll
    for (int wq = 0; wq < 4; wq++)
        if (wq < wid) wbase += wsum[wq];
    int off = wbase + inc - cnt;             // exclusive offset
    if (t == 127) totK = off + cnt;

    // emit bit indices in ascending order
    int base0 = (2 * t) << 5;
    while (m0) {
        int b = __ffs(m0) - 1; m0 &= m0 - 1;
        if (off < CAP) nbr[off] = (unsigned short)(base0 + b);
        off++;
    }
    int base1 = (2 * t + 1) << 5;
    while (m1) {
        int b = __ffs(m1) - 1; m1 &= m1 - 1;
        if (off < CAP) nbr[off] = (unsigned short)(base1 + b);
        off++;
    }
    __syncthreads();
    int K = totK;

    int g = t >> 5;    // 0..3: neighbor stream (walks k = g, g+4, g+8, ...)
    int c = t & 31;    // col chunk: half2 cols 2c, 2c+1 (cols 4c..4c+3)

    const uint2* yv = reinterpret_cast<const uint2*>(g_yh);   // [row][32]

    float2 f0 = make_float2(0.f, 0.f), f1 = f0;

    if (K <= CAP) {
        int k = g;
        for (; k + 12 < K; k += 16) {
            int j0 = nbr[k], j1 = nbr[k + 4], j2 = nbr[k + 8], j3 = nbr[k + 12];
            uint2 v0 = yv[j0 * 32 + c];
            uint2 v1 = yv[j1 * 32 + c];
            uint2 v2 = yv[j2 * 32 + c];
            uint2 v3 = yv[j3 * 32 + c];
            unsigned s0 = hadd2(hadd2(v0.x, v1.x), hadd2(v2.x, v3.x));
            unsigned s1 = hadd2(hadd2(v0.y, v1.y), hadd2(v2.y, v3.y));
            float2 q0 = h2f2(s0), q1 = h2f2(s1);
            f0.x += q0.x; f0.y += q0.y;
            f1.x += q1.x; f1.y += q1.y;
        }
        for (; k < K; k += 4) {
            uint2 v = yv[nbr[k] * 32 + c];
            float2 q0 = h2f2(v.x), q1 = h2f2(v.y);
            f0.x += q0.x; f0.y += q0.y;
            f1.x += q1.x; f1.y += q1.y;
        }
    } else {
        // overflow fallback — structurally impossible here, kept for safety.
        if (g == 0) {
            for (int w = 0; w < words; w++) {
                unsigned m = g_mask[(size_t)i * words + w];
                while (m) {
                    int b = __ffs(m) - 1; m &= m - 1;
                    int j = (w << 5) + b;
                    uint2 v = yv[j * 32 + c];
                    float2 q0 = h2f2(v.x), q1 = h2f2(v.y);
                    f0.x += q0.x; f0.y += q0.y;
                    f1.x += q1.x; f1.y += q1.y;
                }
            }
        }
    }

    part[g * 64 + 2 * c + 0] = f0;
    part[g * 64 + 2 * c + 1] = f1;
    __syncthreads();

    // epilogue: re-zero this row's mask (after Phase B barrier, so the
    // overflow fallback has already consumed it).
    mrow[t] = make_uint2(0u, 0u);

    if (t < 64) {
        float2 s = part[t];
        #pragma unroll
        for (int q = 1; q < 4; q++) {
            float2 pv = part[q * 64 + t];
            s.x += pv.x; s.y += pv.y;
        }
        float dv = rsqrtf((float)g_deg[i] + 1e-8f);
        float2 bb = reinterpret_cast<const float2*>(bias)[t];
        float2 o;
        o.x = fmaf(dv, s.x, bb.x);
        o.y = fmaf(dv, s.y, bb.y);
        reinterpret_cast<float2*>(out)[(size_t)i * 64 + t] = o;
    }
}

// ---------------------------------------------------------------------------
extern "C" void kernel_launch(void* const* d_in, const int* in_sizes, int n_in,
                              void* d_out, int out_size) {
    const float* x    = (const float*)d_in[0];
    const int*   edge = (const int*)d_in[1];
    const float* W    = (const float*)d_in[2];
    const float* b    = (const float*)d_in[3];
    float*       out  = (float*)d_out;

    int N = in_sizes[0] / D;        // 8192
    int E = in_sizes[1] / 2;        // 262144

    k_zero<<<64, 256>>>(W, N);
    int total = E + N;
    k_build<<<(total + 255) / 256, 256>>>(edge, E, N);
    k_gemm_y<<<(N + BR - 1) / BR, 256>>>(x, N);
    k_aggregate<<<N, D>>>(b, out, N);
}

// round 16
// speedup vs baseline: 1.0009x; 1.0009x over previous
#include <cuda_runtime.h>
#include <cuda_fp16.h>
#include <cstdint>

// Problem constants (from reference setup_inputs)
#define NMAX 8192
#define D    128
#define MASK_WORDS ((size_t)NMAX * NMAX / 32)   // 2,097,152 words = 8 MB
#define CAP  2048                               // neighbor-list capacity per row

// Scratch (static device globals — no allocation in kernel_launch)
// g_mask and g_deg are zero-initialized at module load; k_aggregate re-zeroes
// both in its epilogue, so every kernel_launch starts from the same state.
__device__ unsigned g_mask[MASK_WORDS];          // adjacency bitmask, row = src
__device__ int      g_deg[NMAX];                 // distinct-neighbor degree (incl. self loop)
__device__ __half2  g_yh[NMAX * 64];             // y' = dinv[row]*(x@W^T)[row], fp16
__device__ float2   g_wt2[64 * D];               // W^T packed k-pair-interleaved

// packed dual-fp32 fma: d.lo += a.lo*b.lo ; d.hi += a.hi*b.hi
__device__ __forceinline__ void ffma2(unsigned long long& d,
                                      unsigned long long a,
                                      unsigned long long b) {
    asm("fma.rn.f32x2 %0, %1, %2, %0;" : "+l"(d) : "l"(a), "l"(b));
}
__device__ __forceinline__ float f32x2_hsum(unsigned long long v) {
    float lo, hi;
    asm("mov.b64 {%0,%1}, %2;" : "=f"(lo), "=f"(hi) : "l"(v));
    return lo + hi;
}
// packed fp16 add on raw uint32 half2 bits
__device__ __forceinline__ unsigned hadd2(unsigned a, unsigned b) {
    unsigned r;
    asm("add.rn.f16x2 %0, %1, %2;" : "=r"(r) : "r"(a), "r"(b));
    return r;
}
__device__ __forceinline__ float2 h2f2(unsigned s) {
    return __half22float2(*reinterpret_cast<__half2*>(&s));
}

// ---------------------------------------------------------------------------
// 1) edges: set bits (+ self loops), dedup degree count on first-set only.
//    ALSO packs Wt2 (threads t < 64*D; write-only, consumed by later launch).
//    edge_index is int32 (JAX x64-disabled downcasts the requested int64)
__global__ void k_build(const int* __restrict__ edge,
                        const float* __restrict__ W, int E, int N) {
    int t = blockIdx.x * blockDim.x + threadIdx.x;
    if (t < 64 * D) {
        int col = t & 127;
        int kp  = t >> 7;
        g_wt2[kp * D + col] = make_float2(W[col * D + 2 * kp],
                                          W[col * D + 2 * kp + 1]);
    }
    int total = E + N;
    if (t >= total) return;
    int s, d;
    if (t < E) {
        s = edge[t];        // edge_index[0, t] = src
        d = edge[E + t];    // edge_index[1, t] = dst
    } else {
        s = d = t - E;      // self loop
    }
    s &= (NMAX - 1);
    d &= (NMAX - 1);
    int bitpos = s * N + d;
    unsigned bit = 1u << (bitpos & 31);
    unsigned old = atomicOr(&g_mask[bitpos >> 5], bit);
    if (!(old & bit)) atomicAdd(&g_deg[s], 1);
}

// ---------------------------------------------------------------------------
// 2) y' = dinv .* (x @ W^T)  via packed f32x2 FMA, fp16 output.
//    16 rows/block, 256 threads: cp = t&63 -> cols (2cp, 2cp+1),
//    ry = t>>6 -> rows 4ry..4ry+3. Batched broadcast LDS; W register-
//    prefetched DEPTH 2 (4 LDG.128 in flight per thread).  [R14 form, 34.0us]
#define BR 16
__global__ void __launch_bounds__(256) k_gemm_y(const float* __restrict__ x, int N) {
    __shared__ float4 xs[BR * 32];   // [row][kk4], 8 KB

    int t = threadIdx.x;             // 0..255
    int row0 = blockIdx.x * BR;

    const float4* xg = reinterpret_cast<const float4*>(x) + (size_t)row0 * 32;
    int lim = (N - row0) * 32;
    xs[t]       = (t < lim)       ? xg[t]       : make_float4(0.f, 0.f, 0.f, 0.f);
    xs[t + 256] = (t + 256 < lim) ? xg[t + 256] : make_float4(0.f, 0.f, 0.f, 0.f);
    __syncthreads();

    int cp = t & 63;                 // col-pair: cols 2cp, 2cp+1
    int ry = t >> 6;                 // 0..3 -> rows 4ry..4ry+3
    int r0 = 4 * ry;

    const ulonglong2* xv = reinterpret_cast<const ulonglong2*>(xs);
    const ulonglong2* wv = reinterpret_cast<const ulonglong2*>(g_wt2);

    unsigned long long acc[4][2];
    #pragma unroll
    for (int r = 0; r < 4; r++) { acc[r][0] = 0ull; acc[r][1] = 0ull; }

    // depth-2 W prefetch: wa = current kk, wb = next kk; fetch kk+2 each iter
    ulonglong2 wa0 = wv[0 * 64 + cp], wa1 = wv[1 * 64 + cp];   // kk = 0
    ulonglong2 wb0 = wv[2 * 64 + cp], wb1 = wv[3 * 64 + cp];   // kk = 1

    #pragma unroll
    for (int kk = 0; kk < 32; kk++) {
        ulonglong2 xa0 = xv[(r0 + 0) * 32 + kk];
        ulonglong2 xa1 = xv[(r0 + 1) * 32 + kk];
        ulonglong2 xa2 = xv[(r0 + 2) * 32 + kk];
        ulonglong2 xa3 = xv[(r0 + 3) * 32 + kk];
        ulonglong2 nw0, nw1;
        if (kk < 30) {                          // prefetch kk+2's W pair
            nw0 = wv[(2 * kk + 4) * 64 + cp];
            nw1 = wv[(2 * kk + 5) * 64 + cp];
        }
        ffma2(acc[0][0], xa0.x, wa0.x); ffma2(acc[0][1], xa0.x, wa0.y);
        ffma2(acc[1][0], xa1.x, wa0.x); ffma2(acc[1][1], xa1.x, wa0.y);
        ffma2(acc[2][0], xa2.x, wa0.x); ffma2(acc[2][1], xa2.x, wa0.y);
        ffma2(acc[3][0], xa3.x, wa0.x); ffma2(acc[3][1], xa3.x, wa0.y);
        ffma2(acc[0][0], xa0.y, wa1.x); ffma2(acc[0][1], xa0.y, wa1.y);
        ffma2(acc[1][0], xa1.y, wa1.x); ffma2(acc[1][1], xa1.y, wa1.y);
        ffma2(acc[2][0], xa2.y, wa1.x); ffma2(acc[2][1], xa2.y, wa1.y);
        ffma2(acc[3][0], xa3.y, wa1.x); ffma2(acc[3][1], xa3.y, wa1.y);
        wa0 = wb0; wa1 = wb1;
        wb0 = nw0; wb1 = nw1;
    }

    #pragma unroll
    for (int r = 0; r < 4; r++) {
        int row = row0 + r0 + r;
        if (row < N) {
            float dv = rsqrtf((float)g_deg[row] + 1e-8f);
            float sx = f32x2_hsum(acc[r][0]) * dv;
            float sy = f32x2_hsum(acc[r][1]) * dv;
            g_yh[(size_t)row * 64 + cp] = __floats2half2_rn(sx, sy);
        }
    }
}

// ---------------------------------------------------------------------------
// 3) out[i] = dinv[i] * sum_{j in nbr(i)} y'[j]  + b
//    Phase A: direct uint2 mask load + warp scans + ordered emit.
//    Phase B: 4 streams x 32 threads, uint2 (4 cols) per neighbor,
//    HADD2 tree per 4 neighbors, fp32 master accumulators, fixed-order
//    4-way reduce. Deterministic.
//    Epilogue: re-zero this row's mask words AND g_deg[i] (replaces k_zero).
__global__ void k_aggregate(const float* __restrict__ bias,
                            float* __restrict__ out, int N) {
    int i = blockIdx.x;
    int t = threadIdx.x;   // 0..127
    int words = N >> 5;    // 256

    __shared__ unsigned short nbr[CAP];      // 4 KB
    __shared__ float2 part[4 * 64];          // 2 KB
    __shared__ int wsum[4];
    __shared__ int totK;

    // read this row's dinv NOW (before any epilogue zeroing below)
    float dv = rsqrtf((float)g_deg[i] + 1e-8f);

    // direct global load: thread t owns words 2t, 2t+1 (coalesced uint2)
    uint2* mrow = reinterpret_cast<uint2*>(g_mask + (size_t)i * words);
    uint2 mw = mrow[t];
    unsigned m0 = mw.x, m1 = mw.y;
    int cnt = __popc(m0) + __popc(m1);

    // inclusive warp scan of counts
    int lane = t & 31, wid = t >> 5;
    int inc = cnt;
    #pragma unroll
    for (int dd = 1; dd < 32; dd <<= 1) {
        int v = __shfl_up_sync(0xffffffffu, inc, dd);
        if (lane >= dd) inc += v;
    }
    if (lane == 31) wsum[wid] = inc;
    __syncthreads();
    int wbase = 0;
    #pragma unroll
    for (int wq = 0; wq < 4; wq++)
        if (wq < wid) wbase += wsum[wq];
    int off = wbase + inc - cnt;             // exclusive offset
    if (t == 127) totK = off + cnt;

    // emit bit indices in ascending order
    int base0 = (2 * t) << 5;
    while (m0) {
        int b = __ffs(m0) - 1; m0 &= m0 - 1;
        if (off < CAP) nbr[off] = (unsigned short)(base0 + b);
        off++;
    }
    int base1 = (2 * t + 1) << 5;
    while (m1) {
        int b = __ffs(m1) - 1; m1 &= m1 - 1;
        if (off < CAP) nbr[off] = (unsigned short)(base1 + b);
        off++;
    }
    __syncthreads();
    int K = totK;

    int g = t >> 5;    // 0..3: neighbor stream (walks k = g, g+4, g+8, ...)
    int c = t & 31;    // col chunk: half2 cols 2c, 2c+1 (cols 4c..4c+3)

    const uint2* yv = reinterpret_cast<const uint2*>(g_yh);   // [row][32]

    float2 f0 = make_float2(0.f, 0.f), f1 = f0;

    if (K <= CAP) {
        int k = g;
        for (; k + 12 < K; k += 16) {
            int j0 = nbr[k], j1 = nbr[k + 4], j2 = nbr[k + 8], j3 = nbr[k + 12];
            uint2 v0 = yv[j0 * 32 + c];
            uint2 v1 = yv[j1 * 32 + c];
            uint2 v2 = yv[j2 * 32 + c];
            uint2 v3 = yv[j3 * 32 + c];
            unsigned s0 = hadd2(hadd2(v0.x, v1.x), hadd2(v2.x, v3.x));
            unsigned s1 = hadd2(hadd2(v0.y, v1.y), hadd2(v2.y, v3.y));
            float2 q0 = h2f2(s0), q1 = h2f2(s1);
            f0.x += q0.x; f0.y += q0.y;
            f1.x += q1.x; f1.y += q1.y;
        }
        for (; k < K; k += 4) {
            uint2 v = yv[nbr[k] * 32 + c];
            float2 q0 = h2f2(v.x), q1 = h2f2(v.y);
            f0.x += q0.x; f0.y += q0.y;
            f1.x += q1.x; f1.y += q1.y;
        }
    } else {
        // overflow fallback — structurally impossible here, kept for safety.
        if (g == 0) {
            for (int w = 0; w < words; w++) {
                unsigned m = g_mask[(size_t)i * words + w];
                while (m) {
                    int b = __ffs(m) - 1; m &= m - 1;
                    int j = (w << 5) + b;
                    uint2 v = yv[j * 32 + c];
                    float2 q0 = h2f2(v.x), q1 = h2f2(v.y);
                    f0.x += q0.x; f0.y += q0.y;
                    f1.x += q1.x; f1.y += q1.y;
                }
            }
        }
    }

    part[g * 64 + 2 * c + 0] = f0;
    part[g * 64 + 2 * c + 1] = f1;
    __syncthreads();

    // epilogue: re-zero this row's mask + degree (after Phase B barrier, so
    // the overflow fallback and the dv read above have already consumed them).
    mrow[t] = make_uint2(0u, 0u);
    if (t == 127) g_deg[i] = 0;

    if (t < 64) {
        float2 s = part[t];
        #pragma unroll
        for (int q = 1; q < 4; q++) {
            float2 pv = part[q * 64 + t];
            s.x += pv.x; s.y += pv.y;
        }
        float2 bb = reinterpret_cast<const float2*>(bias)[t];
        float2 o;
        o.x = fmaf(dv, s.x, bb.x);
        o.y = fmaf(dv, s.y, bb.y);
        reinterpret_cast<float2*>(out)[(size_t)i * 64 + t] = o;
    }
}

// ---------------------------------------------------------------------------
extern "C" void kernel_launch(void* const* d_in, const int* in_sizes, int n_in,
                              void* d_out, int out_size) {
    const float* x    = (const float*)d_in[0];
    const int*   edge = (const int*)d_in[1];
    const float* W    = (const float*)d_in[2];
    const float* b    = (const float*)d_in[3];
    float*       out  = (float*)d_out;

    int N = in_sizes[0] / D;        // 8192
    int E = in_sizes[1] / 2;        // 262144

    int total = E + N;
    k_build<<<(total + 255) / 256, 256>>>(edge, W, E, N);
    k_gemm_y<<<(N + BR - 1) / BR, 256>>>(x, N);
    k_aggregate<<<N, D>>>(b, out, N);
}

// round 17
// speedup vs baseline: 1.1323x; 1.1313x over previous
#include <cuda_runtime.h>
#include <cuda_fp16.h>
#include <cstdint>

// Problem constants (from reference setup_inputs)
#define NMAX 8192
#define D    128
#define MASK_WORDS ((size_t)NMAX * NMAX / 32)   // 2,097,152 words = 8 MB
#define CAP  2048                               // neighbor-list capacity per row

// Scratch (static device globals — no allocation in kernel_launch)
// g_mask is zero-initialized at module load; k_aggregate re-zeroes the rows it
// consumes, so the mask is all-zero again at the end of every kernel_launch.
// g_dinv/g_yh/g_wt2 are fully overwritten every launch.
__device__ unsigned g_mask[MASK_WORDS];          // adjacency bitmask, row = src
__device__ float    g_dinv[NMAX];                // (distinct degree + eps)^-0.5
__device__ __half2  g_yh[NMAX * 64];             // y' = dinv[row]*(x@W^T)[row], fp16
__device__ float2   g_wt2[64 * D];               // W^T packed k-pair-interleaved

// packed dual-fp32 fma: d.lo += a.lo*b.lo ; d.hi += a.hi*b.hi
__device__ __forceinline__ void ffma2(unsigned long long& d,
                                      unsigned long long a,
                                      unsigned long long b) {
    asm("fma.rn.f32x2 %0, %1, %2, %0;" : "+l"(d) : "l"(a), "l"(b));
}
__device__ __forceinline__ float f32x2_hsum(unsigned long long v) {
    float lo, hi;
    asm("mov.b64 {%0,%1}, %2;" : "=f"(lo), "=f"(hi) : "l"(v));
    return lo + hi;
}
// packed fp16 add on raw uint32 half2 bits
__device__ __forceinline__ unsigned hadd2(unsigned a, unsigned b) {
    unsigned r;
    asm("add.rn.f16x2 %0, %1, %2;" : "=r"(r) : "r"(a), "r"(b));
    return r;
}
__device__ __forceinline__ float2 h2f2(unsigned s) {
    return __half22float2(*reinterpret_cast<__half2*>(&s));
}

// ---------------------------------------------------------------------------
// 1) edges: fire-and-forget RED.OR into the bitmask (+ self loops).
//    No return value consumed -> ptxas emits RED (no round-trip wait).
//    ALSO packs Wt2 (threads t < 64*D; write-only, consumed later).
//    edge_index is int32 (JAX x64-disabled downcasts the requested int64)
__global__ void k_build(const int* __restrict__ edge,
                        const float* __restrict__ W, int E, int N) {
    int t = blockIdx.x * blockDim.x + threadIdx.x;
    if (t < 64 * D) {
        int col = t & 127;
        int kp  = t >> 7;
        g_wt2[kp * D + col] = make_float2(W[col * D + 2 * kp],
                                          W[col * D + 2 * kp + 1]);
    }
    int total = E + N;
    if (t >= total) return;
    int s, d;
    if (t < E) {
        s = edge[t];        // edge_index[0, t] = src
        d = edge[E + t];    // edge_index[1, t] = dst
    } else {
        s = d = t - E;      // self loop
    }
    s &= (NMAX - 1);
    d &= (NMAX - 1);
    int bitpos = s * N + d;
    atomicOr(&g_mask[bitpos >> 5], 1u << (bitpos & 31));   // result unused -> RED
}

// ---------------------------------------------------------------------------
// 2) degrees by popcount: one warp per row; dedup is inherent in the bitmask.
//    Writes dinv directly (fully overwritten every launch).
__global__ void k_deg(int N) {
    int row  = (blockIdx.x * blockDim.x + threadIdx.x) >> 5;
    int lane = threadIdx.x & 31;
    if (row >= N) return;
    const uint2* mrow = reinterpret_cast<const uint2*>(g_mask + (size_t)row * (N >> 5));
    int cnt = 0;
    #pragma unroll
    for (int q = 0; q < 4; q++) {           // 128 uint2 per row, 4 per lane
        uint2 v = mrow[lane + q * 32];
        cnt += __popc(v.x) + __popc(v.y);
    }
    cnt = __reduce_add_sync(0xffffffffu, cnt);
    if (lane == 0) g_dinv[row] = rsqrtf((float)cnt + 1e-8f);
}

// ---------------------------------------------------------------------------
// 3) y' = dinv .* (x @ W^T)  via packed f32x2 FMA, fp16 output.
//    16 rows/block, 256 threads: cp = t&63 -> cols (2cp, 2cp+1),
//    ry = t>>6 -> rows 4ry..4ry+3. Batched broadcast LDS; W register-
//    prefetched DEPTH 2 (4 LDG.128 in flight per thread).
#define BR 16
__global__ void __launch_bounds__(256) k_gemm_y(const float* __restrict__ x, int N) {
    __shared__ float4 xs[BR * 32];   // [row][kk4], 8 KB

    int t = threadIdx.x;             // 0..255
    int row0 = blockIdx.x * BR;

    const float4* xg = reinterpret_cast<const float4*>(x) + (size_t)row0 * 32;
    int lim = (N - row0) * 32;
    xs[t]       = (t < lim)       ? xg[t]       : make_float4(0.f, 0.f, 0.f, 0.f);
    xs[t + 256] = (t + 256 < lim) ? xg[t + 256] : make_float4(0.f, 0.f, 0.f, 0.f);
    __syncthreads();

    int cp = t & 63;                 // col-pair: cols 2cp, 2cp+1
    int ry = t >> 6;                 // 0..3 -> rows 4ry..4ry+3
    int r0 = 4 * ry;

    const ulonglong2* xv = reinterpret_cast<const ulonglong2*>(xs);
    const ulonglong2* wv = reinterpret_cast<const ulonglong2*>(g_wt2);

    unsigned long long acc[4][2];
    #pragma unroll
    for (int r = 0; r < 4; r++) { acc[r][0] = 0ull; acc[r][1] = 0ull; }

    // depth-2 W prefetch: wa = current kk, wb = next kk; fetch kk+2 each iter
    ulonglong2 wa0 = wv[0 * 64 + cp], wa1 = wv[1 * 64 + cp];   // kk = 0
    ulonglong2 wb0 = wv[2 * 64 + cp], wb1 = wv[3 * 64 + cp];   // kk = 1

    #pragma unroll
    for (int kk = 0; kk < 32; kk++) {
        ulonglong2 xa0 = xv[(r0 + 0) * 32 + kk];
        ulonglong2 xa1 = xv[(r0 + 1) * 32 + kk];
        ulonglong2 xa2 = xv[(r0 + 2) * 32 + kk];
        ulonglong2 xa3 = xv[(r0 + 3) * 32 + kk];
        ulonglong2 nw0, nw1;
        if (kk < 30) {                          // prefetch kk+2's W pair
            nw0 = wv[(2 * kk + 4) * 64 + cp];
            nw1 = wv[(2 * kk + 5) * 64 + cp];
        }
        ffma2(acc[0][0], xa0.x, wa0.x); ffma2(acc[0][1], xa0.x, wa0.y);
        ffma2(acc[1][0], xa1.x, wa0.x); ffma2(acc[1][1], xa1.x, wa0.y);
        ffma2(acc[2][0], xa2.x, wa0.x); ffma2(acc[2][1], xa2.x, wa0.y);
        ffma2(acc[3][0], xa3.x, wa0.x); ffma2(acc[3][1], xa3.x, wa0.y);
        ffma2(acc[0][0], xa0.y, wa1.x); ffma2(acc[0][1], xa0.y, wa1.y);
        ffma2(acc[1][0], xa1.y, wa1.x); ffma2(acc[1][1], xa1.y, wa1.y);
        ffma2(acc[2][0], xa2.y, wa1.x); ffma2(acc[2][1], xa2.y, wa1.y);
        ffma2(acc[3][0], xa3.y, wa1.x); ffma2(acc[3][1], xa3.y, wa1.y);
        wa0 = wb0; wa1 = wb1;
        wb0 = nw0; wb1 = nw1;
    }

    #pragma unroll
    for (int r = 0; r < 4; r++) {
        int row = row0 + r0 + r;
        if (row < N) {
            float dv = g_dinv[row];
            float sx = f32x2_hsum(acc[r][0]) * dv;
            float sy = f32x2_hsum(acc[r][1]) * dv;
            g_yh[(size_t)row * 64 + cp] = __floats2half2_rn(sx, sy);
        }
    }
}

// ---------------------------------------------------------------------------
// 4) out[i] = dinv[i] * sum_{j in nbr(i)} y'[j]  + b
//    Phase A: direct uint2 mask load + warp scans + ordered emit.
//    Phase B: 4 streams x 32 threads, uint2 (4 cols) per neighbor,
//    HADD2 tree per 4 neighbors, fp32 master accumulators, fixed-order
//    4-way reduce. Deterministic.
//    Epilogue: re-zero this row's mask words.
__global__ void k_aggregate(const float* __restrict__ bias,
                            float* __restrict__ out, int N) {
    int i = blockIdx.x;
    int t = threadIdx.x;   // 0..127
    int words = N >> 5;    // 256

    __shared__ unsigned short nbr[CAP];      // 4 KB
    __shared__ float2 part[4 * 64];          // 2 KB
    __shared__ int wsum[4];
    __shared__ int totK;

    float dv = g_dinv[i];

    // direct global load: thread t owns words 2t, 2t+1 (coalesced uint2)
    uint2* mrow = reinterpret_cast<uint2*>(g_mask + (size_t)i * words);
    uint2 mw = mrow[t];
    unsigned m0 = mw.x, m1 = mw.y;
    int cnt = __popc(m0) + __popc(m1);

    // inclusive warp scan of counts
    int lane = t & 31, wid = t >> 5;
    int inc = cnt;
    #pragma unroll
    for (int dd = 1; dd < 32; dd <<= 1) {
        int v = __shfl_up_sync(0xffffffffu, inc, dd);
        if (lane >= dd) inc += v;
    }
    if (lane == 31) wsum[wid] = inc;
    __syncthreads();
    int wbase = 0;
    #pragma unroll
    for (int wq = 0; wq < 4; wq++)
        if (wq < wid) wbase += wsum[wq];
    int off = wbase + inc - cnt;             // exclusive offset
    if (t == 127) totK = off + cnt;

    // emit bit indices in ascending order
    int base0 = (2 * t) << 5;
    while (m0) {
        int b = __ffs(m0) - 1; m0 &= m0 - 1;
        if (off < CAP) nbr[off] = (unsigned short)(base0 + b);
        off++;
    }
    int base1 = (2 * t + 1) << 5;
    while (m1) {
        int b = __ffs(m1) - 1; m1 &= m1 - 1;
        if (off < CAP) nbr[off] = (unsigned short)(base1 + b);
        off++;
    }
    __syncthreads();
    int K = totK;

    int g = t >> 5;    // 0..3: neighbor stream (walks k = g, g+4, g+8, ...)
    int c = t & 31;    // col chunk: half2 cols 2c, 2c+1 (cols 4c..4c+3)

    const uint2* yv = reinterpret_cast<const uint2*>(g_yh);   // [row][32]

    float2 f0 = make_float2(0.f, 0.f), f1 = f0;

    if (K <= CAP) {
        int k = g;
        for (; k + 12 < K; k += 16) {
            int j0 = nbr[k], j1 = nbr[k + 4], j2 = nbr[k + 8], j3 = nbr[k + 12];
            uint2 v0 = yv[j0 * 32 + c];
            uint2 v1 = yv[j1 * 32 + c];
            uint2 v2 = yv[j2 * 32 + c];
            uint2 v3 = yv[j3 * 32 + c];
            unsigned s0 = hadd2(hadd2(v0.x, v1.x), hadd2(v2.x, v3.x));
            unsigned s1 = hadd2(hadd2(v0.y, v1.y), hadd2(v2.y, v3.y));
            float2 q0 = h2f2(s0), q1 = h2f2(s1);
            f0.x += q0.x; f0.y += q0.y;
            f1.x += q1.x; f1.y += q1.y;
        }
        for (; k < K; k += 4) {
            uint2 v = yv[nbr[k] * 32 + c];
            float2 q0 = h2f2(v.x), q1 = h2f2(v.y);
            f0.x += q0.x; f0.y += q0.y;
            f1.x += q1.x; f1.y += q1.y;
        }
    } else {
        // overflow fallback — structurally impossible here, kept for safety.
        if (g == 0) {
            for (int w = 0; w < words; w++) {
                unsigned m = g_mask[(size_t)i * words + w];
                while (m) {
                    int b = __ffs(m) - 1; m &= m - 1;
                    int j = (w << 5) + b;
                    uint2 v = yv[j * 32 + c];
                    float2 q0 = h2f2(v.x), q1 = h2f2(v.y);
                    f0.x += q0.x; f0.y += q0.y;
                    f1.x += q1.x; f1.y += q1.y;
                }
            }
        }
    }

    part[g * 64 + 2 * c + 0] = f0;
    part[g * 64 + 2 * c + 1] = f1;
    __syncthreads();

    // epilogue: re-zero this row's mask (after Phase B barrier, so the
    // overflow fallback has already consumed it).
    mrow[t] = make_uint2(0u, 0u);

    if (t < 64) {
        float2 s = part[t];
        #pragma unroll
        for (int q = 1; q < 4; q++) {
            float2 pv = part[q * 64 + t];
            s.x += pv.x; s.y += pv.y;
        }
        float2 bb = reinterpret_cast<const float2*>(bias)[t];
        float2 o;
        o.x = fmaf(dv, s.x, bb.x);
        o.y = fmaf(dv, s.y, bb.y);
        reinterpret_cast<float2*>(out)[(size_t)i * 64 + t] = o;
    }
}

// ---------------------------------------------------------------------------
extern "C" void kernel_launch(void* const* d_in, const int* in_sizes, int n_in,
                              void* d_out, int out_size) {
    const float* x    = (const float*)d_in[0];
    const int*   edge = (const int*)d_in[1];
    const float* W    = (const float*)d_in[2];
    const float* b    = (const float*)d_in[3];
    float*       out  = (float*)d_out;

    int N = in_sizes[0] / D;        // 8192
    int E = in_sizes[1] / 2;        // 262144

    int total = E + N;
    k_build<<<(total + 255) / 256, 256>>>(edge, W, E, N);
    k_deg<<<(N * 32 + 255) / 256, 256>>>(N);
    k_gemm_y<<<(N + BR - 1) / BR, 256>>>(x, N);
    k_aggregate<<<N, D>>>(b, out, N);
}